// round 16
// baseline (speedup 1.0000x reference)
#include <cuda_runtime.h>
#include <cuda_fp16.h>
#include <cstdint>

// Problem constants
#define IN_CH   4096
#define OUT_CH  4096
#define BATCH   8192

// Sparse GEMM tiling: D[out, batch] = Wsp[out, k] * x^T[k, batch]
#define TMO     128                  // out rows per CTA (M)
#define TNB     128                  // batch cols per CTA (N)
#define KC      64                   // original k per chunk
#define NCHUNK  (IN_CH / KC)         // 64
#define NSTAGE  3
#define NTHREADS 128                 // 4 warps: wm (M half) x wn (N half), warp tile 64x64

// smem stage: A cmp (128 rows x 128B padded) | B (128 x 128B) | meta (1 KB)
#define A_BYTES     16384
#define B_BYTES     16384
#define M_BYTES     1024
#define STAGE_BYTES 33792            // 33 KB aligned
#define OFF_B       16384
#define OFF_M       32768
#define SMEM_TOTAL  (NSTAGE * STAGE_BYTES)   // 101376 -> 2 CTAs/SM
#define FIX_SMEM    (128 * 129 * 4)          // 66048

// Scratch (device globals; allocation-free per harness rules)
__device__ __half  g_xh [(size_t)BATCH * IN_CH];          // x fp16 [b][k]
__device__ __half  g_xT [(size_t)IN_CH * BATCH];          // x fp16 transposed [k][b]
__device__ __half  g_wh [(size_t)OUT_CH * IN_CH];         // dense W fp16
__device__ __half  g_cw [(size_t)OUT_CH * (IN_CH / 2)];   // 2:4 compressed W
__device__ unsigned short g_mtm[(size_t)(OUT_CH / 16) * 8 * (IN_CH / 16) * 2]; // metadata
__device__ int     g_ocnt[OUT_CH];                        // overflow counts per out-row
__device__ int2    g_ofl [OUT_CH * 16];                   // overflow {k, w_bits}

// ---------------------------------------------------------------------------
// PTX helpers
// ---------------------------------------------------------------------------
__device__ __forceinline__ uint32_t smem_u32(const void* p) {
    uint32_t a;
    asm("{ .reg .u64 t; cvta.to.shared.u64 t, %1; cvt.u32.u64 %0, t; }"
        : "=r"(a) : "l"(p));
    return a;
}
__device__ __forceinline__ void ldsm4(uint32_t* r, uint32_t addr) {
    asm volatile("ldmatrix.sync.aligned.m8n8.x4.shared.b16 {%0,%1,%2,%3}, [%4];"
                 : "=r"(r[0]), "=r"(r[1]), "=r"(r[2]), "=r"(r[3]) : "r"(addr));
}
__device__ __forceinline__ void mma_sp16(float* d, const uint32_t* a,
                                         const uint32_t* b, uint32_t e) {
    asm volatile(
        "mma.sp.sync.aligned.m16n8k32.row.col.f32.f16.f16.f32 "
        "{%0,%1,%2,%3}, {%4,%5,%6,%7}, {%8,%9,%10,%11}, {%0,%1,%2,%3}, %12, 0x0;"
        : "+f"(d[0]), "+f"(d[1]), "+f"(d[2]), "+f"(d[3])
        : "r"(a[0]), "r"(a[1]), "r"(a[2]), "r"(a[3]),
          "r"(b[0]), "r"(b[1]), "r"(b[2]), "r"(b[3]), "r"(e));
}

// ---------------------------------------------------------------------------
// 1) zero W + overflow counters
// ---------------------------------------------------------------------------
__global__ void k_zero_w() {
    size_t gid = (size_t)blockIdx.x * 256 + threadIdx.x;
    size_t i = gid * 16;   // 16 fp16 = 32 B
    uint4 z = make_uint4(0, 0, 0, 0);
    *reinterpret_cast<uint4*>(&g_wh[i])     = z;
    *reinterpret_cast<uint4*>(&g_wh[i + 8]) = z;
    if (gid < OUT_CH) g_ocnt[gid] = 0;
}

__global__ void k_scatter_w(const float* __restrict__ w, const int* __restrict__ rows,
                            const int* __restrict__ cols, int nnz) {
    int i = blockIdx.x * 256 + threadIdx.x;
    if (i >= nnz) return;
    g_wh[(size_t)rows[i] * IN_CH + cols[i]] = __float2half_rn(w[i]);
}

// ---------------------------------------------------------------------------
// 2) compress dense W -> 2:4 (keep first 2 nnz per group; extras -> overflow)
//    One thread per (row r, 16-k half h).
// ---------------------------------------------------------------------------
__global__ void k_compress() {
    size_t gid = (size_t)blockIdx.x * 256 + threadIdx.x;
    const int r = (int)(gid >> 8);
    const int h = (int)(gid & 255);

    __half hv[16];
    {
        const uint4* p = reinterpret_cast<const uint4*>(&g_wh[(size_t)r * IN_CH + h * 16]);
        uint4 v0 = p[0], v1 = p[1];
        *reinterpret_cast<uint4*>(&hv[0]) = v0;
        *reinterpret_cast<uint4*>(&hv[8]) = v1;
    }
    __half out[8];
    unsigned int m16 = 0;
#pragma unroll
    for (int g = 0; g < 4; g++) {
        int idxs[4], cnt = 0;
#pragma unroll
        for (int k = 0; k < 4; k++) {
            unsigned short bits = reinterpret_cast<unsigned short*>(hv)[g * 4 + k];
            if (bits != 0) idxs[cnt++] = k;
        }
        int i0, i1;
        if (cnt >= 2)      { i0 = idxs[0]; i1 = idxs[1]; }
        else if (cnt == 1) { if (idxs[0] < 2) { i0 = 0; i1 = 1; } else { i0 = 2; i1 = 3; } }
        else               { i0 = 0; i1 = 1; }
        out[g * 2]     = hv[g * 4 + i0];
        out[g * 2 + 1] = hv[g * 4 + i1];
        m16 |= (unsigned int)(i0 | (i1 << 2)) << (4 * g);
        // extras -> overflow (exact fixup terms)
        for (int e = 2; e < cnt; e++) {
            int slot = atomicAdd(&g_ocnt[r], 1);
            if (slot < 16) {
                int c = h * 16 + g * 4 + idxs[e];
                g_ofl[r * 16 + slot] =
                    make_int2(c, __float_as_int(__half2float(hv[g * 4 + idxs[e]])));
            }
        }
    }
    *reinterpret_cast<uint4*>(&g_cw[(size_t)r * (IN_CH / 2) + h * 8]) =
        *reinterpret_cast<uint4*>(out);
    // metadata u16: rows (q, q+8) pairing — low half-word = rows with (r&8)==0
    size_t mi = ((size_t)((r >> 4) * 8 + (r & 7)) * 256 + h) * 2 + ((r >> 3) & 1);
    g_mtm[mi] = (unsigned short)m16;
}

// ---------------------------------------------------------------------------
// 3) x prep: fp32 -> fp16 (g_xh) AND fp16 transpose (g_xT), one kernel.
//    Tile 64 b x 64 c, block (32, 8).
// ---------------------------------------------------------------------------
__global__ void k_xprep(const float* __restrict__ x) {
    __shared__ uint32_t t[64][33];
    const int ch0 = blockIdx.x * 32;       // half2 col base
    const int b0  = blockIdx.y * 64;
    const int tx = threadIdx.x, ty = threadIdx.y;
    const float2* x2 = reinterpret_cast<const float2*>(x);
    __half2* xh2 = reinterpret_cast<__half2*>(g_xh);
    __half2* xT2 = reinterpret_cast<__half2*>(g_xT);
#pragma unroll
    for (int j = 0; j < 8; j++) {
        int row = ty + j * 8;
        float2 v = x2[(size_t)(b0 + row) * 2048 + ch0 + tx];
        __half2 h = __float22half2_rn(v);
        xh2[(size_t)(b0 + row) * 2048 + ch0 + tx] = h;
        t[row][tx] = *reinterpret_cast<uint32_t*>(&h);
    }
    __syncthreads();
    const int tid = ty * 32 + tx;
    const int c0 = ch0 * 2;
#pragma unroll
    for (int it = 0; it < 8; it++) {
        int idx = it * 256 + tid;          // 2048 outputs
        int c_l = idx >> 5;                // 0..63
        int i   = idx & 31;                // b-pair 0..31
        int ch  = c_l >> 1, sel = c_l & 1;
        uint32_t u0 = t[2 * i][ch], u1 = t[2 * i + 1][ch];
        unsigned short lo = sel ? (unsigned short)(u0 >> 16) : (unsigned short)(u0 & 0xFFFF);
        unsigned short hi = sel ? (unsigned short)(u1 >> 16) : (unsigned short)(u1 & 0xFFFF);
        uint32_t packed = (uint32_t)lo | ((uint32_t)hi << 16);
        xT2[(size_t)(c0 + c_l) * 4096 + (b0 >> 1) + i] = *reinterpret_cast<__half2*>(&packed);
    }
}

// ---------------------------------------------------------------------------
// 4) fixup: y = bias + overflow terms (spgemm then ADDS its acc into y).
//    CTA: 128 threads, tile = 128 b x 128 o. smem sY[128][129].
// ---------------------------------------------------------------------------
__global__ void __launch_bounds__(128)
k_fix(const float* __restrict__ bias, float* __restrict__ y) {
    extern __shared__ float sY[];
    const int o0 = blockIdx.x * 128;
    const int b0 = blockIdx.y * 128;
    const int tid = threadIdx.x;

    const float bv = bias[o0 + tid];
#pragma unroll 4
    for (int b = 0; b < 128; b++) sY[b * 129 + tid] = bv;
    __syncthreads();

    for (int rl = 0; rl < 128; rl++) {
        const int r = o0 + rl;
        const int cnt = g_ocnt[r] < 16 ? g_ocnt[r] : 16;
        for (int e = 0; e < cnt; e++) {
            int2 ent = g_ofl[r * 16 + e];
            float w = __int_as_float(ent.y);
            float xv = __half2float(g_xT[(size_t)ent.x * BATCH + b0 + tid]);
            sY[tid * 129 + rl] += w * xv;
        }
    }
    __syncthreads();
#pragma unroll 4
    for (int it = 0; it < 128; it++) {
        int b = it, o = tid;
        y[(size_t)(b0 + b) * OUT_CH + o0 + o] = sY[b * 129 + o];
    }
}

// ---------------------------------------------------------------------------
// cp.async loader: one chunk (Acmp 128x64B-in-128B | B 128x128B | meta 1KB)
// ---------------------------------------------------------------------------
__device__ __forceinline__ void load_chunk(uint32_t sbase, int chunk, int stage,
                                           int m0, int n0, int tid) {
    const int k0 = chunk * KC;
    const uint32_t st = sbase + stage * STAGE_BYTES;
#pragma unroll
    for (int it = 0; it < 13; it++) {
        int j = it * NTHREADS + tid;
        if (j >= 1600) break;
        const void* src;
        uint32_t dst;
        if (j < 512) {                         // A cmp: 128 rows x 4 segs
            int r = j >> 2, s = j & 3;
            src = g_cw + (size_t)(m0 + r) * (IN_CH / 2) + chunk * 32 + s * 8;
            dst = st + (uint32_t)(r * 128 + ((s ^ (r & 7)) << 4));
        } else if (j < 1536) {                 // B (=x): 128 rows x 8 segs
            int jb = j - 512;
            int r = jb >> 3, s = jb & 7;
            src = g_xh + (size_t)(n0 + r) * IN_CH + k0 + s * 8;
            dst = st + OFF_B + (uint32_t)(r * 128 + ((s ^ (r & 7)) << 4));
        } else {                               // meta: 64 x 16B
            int jm = j - 1536;                 // rtl = jm>>3, q = jm&7
            src = reinterpret_cast<const char*>(g_mtm)
                + (size_t)(((m0 >> 4) + (jm >> 3)) * 8 + (jm & 7)) * 1024 + chunk * 16;
            dst = st + OFF_M + (uint32_t)(jm * 16);
        }
        asm volatile("cp.async.cg.shared.global [%0], [%1], 16;" :: "r"(dst), "l"(src));
    }
    asm volatile("cp.async.commit_group;" ::: "memory");
}

// ---------------------------------------------------------------------------
// 5) sparse GEMM: D[128 out x 128 batch] += Wsp * x^T ; epilogue adds into y.
// ---------------------------------------------------------------------------
__global__ void __launch_bounds__(NTHREADS, 2)
k_spgemm(float* __restrict__ y) {
    extern __shared__ char smem[];
    const uint32_t sbase = smem_u32(smem);
    const int tid  = threadIdx.x;
    const int warp = tid >> 5;
    const int lane = tid & 31;
    const int wm   = warp >> 1;           // M half (out)
    const int wn   = warp & 1;            // N half (batch)
    const int m0   = blockIdx.x * TMO;    // out base
    const int n0   = blockIdx.y * TNB;    // batch base

    const uint32_t axor = (uint32_t)(lane & 7);
    uint32_t arow[4];
#pragma unroll
    for (int mt = 0; mt < 4; mt++)
        arow[mt] = (uint32_t)((wm * 64 + mt * 16 + (lane & 15)) * 128);
    const uint32_t aseg = (uint32_t)((lane >> 4) & 1);
    uint32_t brow[8];
#pragma unroll
    for (int j = 0; j < 8; j++)
        brow[j] = (uint32_t)((wn * 64 + j * 8 + (lane & 7)) * 128) + OFF_B;
    const uint32_t bseg = (uint32_t)(lane >> 3);
    const uint32_t mbase = OFF_M + (uint32_t)(((wm * 4) * 8 + (lane >> 2)) * 16
                                              + (lane & 1) * 4);

    float acc[4][8][4];
#pragma unroll
    for (int mt = 0; mt < 4; mt++)
#pragma unroll
        for (int j = 0; j < 8; j++)
#pragma unroll
            for (int q = 0; q < 4; q++) acc[mt][j][q] = 0.0f;

    load_chunk(sbase, 0, 0, m0, n0, tid);
    load_chunk(sbase, 1, 1, m0, n0, tid);

    for (int i = 0; i < NCHUNK; i++) {
        if (i < NCHUNK - 1)
            asm volatile("cp.async.wait_group 1;" ::: "memory");
        else
            asm volatile("cp.async.wait_group 0;" ::: "memory");
        __syncthreads();

        if (i + 2 < NCHUNK)
            load_chunk(sbase, i + 2, (i + 2) % NSTAGE, m0, n0, tid);

        const uint32_t st = sbase + (i % NSTAGE) * STAGE_BYTES;

#pragma unroll
        for (int kt = 0; kt < 2; kt++) {       // 2 x k32 per 64-k chunk
            uint32_t a[4][4], e[4];
#pragma unroll
            for (int mt = 0; mt < 4; mt++) {
                uint32_t seg = (uint32_t)(kt * 2) + aseg;
                ldsm4(a[mt], st + arow[mt] + ((seg ^ axor) << 4));
                asm volatile("ld.shared.b32 %0, [%1];"
                             : "=r"(e[mt]) : "r"(st + mbase + mt * 128 + kt * 8));
            }
#pragma unroll
            for (int j = 0; j < 8; j++) {
                uint32_t b[4];
                uint32_t seg = (uint32_t)(kt * 4) + bseg;
                ldsm4(b, st + brow[j] + ((seg ^ axor) << 4));
#pragma unroll
                for (int mt = 0; mt < 4; mt++)
                    mma_sp16(acc[mt][j], a[mt], b, e[mt]);
            }
        }
    }

    // Epilogue: transpose D through smem, then y += D (y holds bias+overflow)
    __syncthreads();
    float* sD = reinterpret_cast<float*>(smem);
#pragma unroll
    for (int mt = 0; mt < 4; mt++) {
        const int ob = wm * 64 + mt * 16 + (lane >> 2);
#pragma unroll
        for (int j = 0; j < 8; j++) {
            const int bb = wn * 64 + j * 8 + 2 * (lane & 3);
            *reinterpret_cast<float2*>(&sD[ob * 130 + bb]) =
                make_float2(acc[mt][j][0], acc[mt][j][1]);
            *reinterpret_cast<float2*>(&sD[(ob + 8) * 130 + bb]) =
                make_float2(acc[mt][j][2], acc[mt][j][3]);
        }
    }
    __syncthreads();
    {
        float* yrow = y + (size_t)(n0 + tid) * OUT_CH + m0;
#pragma unroll 4
        for (int og = 0; og < 32; og++) {
            float4 v = *reinterpret_cast<float4*>(&yrow[og * 4]);
            v.x += sD[(og * 4 + 0) * 130 + tid];
            v.y += sD[(og * 4 + 1) * 130 + tid];
            v.z += sD[(og * 4 + 2) * 130 + tid];
            v.w += sD[(og * 4 + 3) * 130 + tid];
            *reinterpret_cast<float4*>(&yrow[og * 4]) = v;
        }
    }
}

// ---------------------------------------------------------------------------
// Launch (graph-capturable: kernel launches only, default stream)
// ---------------------------------------------------------------------------
extern "C" void kernel_launch(void* const* d_in, const int* in_sizes, int n_in,
                              void* d_out, int out_size) {
    const float* x    = (const float*)d_in[0];
    const float* w    = (const float*)d_in[1];
    const int*   rows = (const int*)  d_in[2];
    const int*   cols = (const int*)  d_in[3];
    const float* bias = (const float*)d_in[4];
    float*       y    = (float*)d_out;
    const int    nnz  = in_sizes[1];

    cudaFuncSetAttribute(k_spgemm, cudaFuncAttributeMaxDynamicSharedMemorySize,
                         SMEM_TOTAL);
    cudaFuncSetAttribute(k_fix, cudaFuncAttributeMaxDynamicSharedMemorySize,
                         FIX_SMEM);

    k_zero_w<<<(int)(((size_t)OUT_CH * IN_CH / 16) / 256), 256>>>();
    k_scatter_w<<<(nnz + 255) / 256, 256>>>(w, rows, cols, nnz);
    k_compress<<<(OUT_CH * (IN_CH / 16)) / 256, 256>>>();
    k_xprep<<<dim3(IN_CH / 64, BATCH / 64), dim3(32, 8)>>>(x);
    k_fix<<<dim3(OUT_CH / 128, BATCH / 128), 128, FIX_SMEM>>>(bias, y);
    k_spgemm<<<dim3(OUT_CH / TMO, BATCH / TNB), NTHREADS, SMEM_TOTAL>>>(y);
}

// round 17
// speedup vs baseline: 4.5839x; 4.5839x over previous
#include <cuda_runtime.h>
#include <cuda_fp16.h>
#include <cstdint>

// Problem constants
#define IN_CH   4096
#define OUT_CH  4096
#define BATCH   8192

// Sparse GEMM tiling: D[out, batch] = Wsp[out, k] * x^T[k, batch]
#define TMO     128                  // out rows per CTA (M)
#define TNB     128                  // batch cols per CTA (N)
#define KC      64                   // original k per chunk
#define NCHUNK  (IN_CH / KC)         // 64
#define NSTAGE  3
#define NTHREADS 128                 // 4 warps: wm (M half) x wn (N half), warp tile 64x64

// smem stage: A cmp (128 rows x 128B padded) | B (128 x 128B) | meta (1 KB)
#define A_BYTES     16384
#define B_BYTES     16384
#define M_BYTES     1024
#define STAGE_BYTES 33792            // 33 KB aligned
#define OFF_B       16384
#define OFF_M       32768
#define SMEM_TOTAL  (NSTAGE * STAGE_BYTES)   // 101376 -> 2 CTAs/SM
#define FIX_SMEM    (128 * 129 * 4)          // 66048

// Scratch (device globals; allocation-free per harness rules)
__device__ __half  g_xh [(size_t)BATCH * IN_CH];          // x fp16 [b][k]
__device__ __half  g_xT [(size_t)IN_CH * BATCH];          // x fp16 transposed [k][b]
__device__ __half  g_wh [(size_t)OUT_CH * IN_CH];         // dense W fp16
__device__ __half  g_cw [(size_t)OUT_CH * (IN_CH / 2)];   // 2:4 compressed W
__device__ unsigned short g_mtm[(size_t)(OUT_CH / 16) * 8 * (IN_CH / 16) * 2]; // metadata
__device__ int     g_ocnt[OUT_CH];                        // overflow counts per out-row
__device__ int2    g_ofl [OUT_CH * 16];                   // overflow {k, w_bits}

// ---------------------------------------------------------------------------
// PTX helpers
// ---------------------------------------------------------------------------
__device__ __forceinline__ uint32_t smem_u32(const void* p) {
    uint32_t a;
    asm("{ .reg .u64 t; cvta.to.shared.u64 t, %1; cvt.u32.u64 %0, t; }"
        : "=r"(a) : "l"(p));
    return a;
}
__device__ __forceinline__ void ldsm4(uint32_t* r, uint32_t addr) {
    asm volatile("ldmatrix.sync.aligned.m8n8.x4.shared.b16 {%0,%1,%2,%3}, [%4];"
                 : "=r"(r[0]), "=r"(r[1]), "=r"(r[2]), "=r"(r[3]) : "r"(addr));
}
// ordered_metadata: HW sparse path on sm_90+/sm_103 (legacy mma.sp is emulated).
// Metadata layout identical; requires per-group indices sorted ascending,
// which k_compress guarantees (i0 < i1 by ascending scan).
__device__ __forceinline__ void mma_sp16(float* d, const uint32_t* a,
                                         const uint32_t* b, uint32_t e) {
    asm volatile(
        "mma.sp::ordered_metadata.sync.aligned.m16n8k32.row.col.f32.f16.f16.f32 "
        "{%0,%1,%2,%3}, {%4,%5,%6,%7}, {%8,%9,%10,%11}, {%0,%1,%2,%3}, %12, 0x0;"
        : "+f"(d[0]), "+f"(d[1]), "+f"(d[2]), "+f"(d[3])
        : "r"(a[0]), "r"(a[1]), "r"(a[2]), "r"(a[3]),
          "r"(b[0]), "r"(b[1]), "r"(b[2]), "r"(b[3]), "r"(e));
}

// ---------------------------------------------------------------------------
// 1) zero W + overflow counters
// ---------------------------------------------------------------------------
__global__ void k_zero_w() {
    size_t gid = (size_t)blockIdx.x * 256 + threadIdx.x;
    size_t i = gid * 16;   // 16 fp16 = 32 B
    uint4 z = make_uint4(0, 0, 0, 0);
    *reinterpret_cast<uint4*>(&g_wh[i])     = z;
    *reinterpret_cast<uint4*>(&g_wh[i + 8]) = z;
    if (gid < OUT_CH) g_ocnt[gid] = 0;
}

__global__ void k_scatter_w(const float* __restrict__ w, const int* __restrict__ rows,
                            const int* __restrict__ cols, int nnz) {
    int i = blockIdx.x * 256 + threadIdx.x;
    if (i >= nnz) return;
    g_wh[(size_t)rows[i] * IN_CH + cols[i]] = __float2half_rn(w[i]);
}

// ---------------------------------------------------------------------------
// 2) compress dense W -> 2:4 (keep first 2 nnz per group; extras -> overflow)
//    One thread per (row r, 16-k half h). Emitted indices are sorted (i0<i1),
//    satisfying the ordered_metadata requirement.
// ---------------------------------------------------------------------------
__global__ void k_compress() {
    size_t gid = (size_t)blockIdx.x * 256 + threadIdx.x;
    const int r = (int)(gid >> 8);
    const int h = (int)(gid & 255);

    __half hv[16];
    {
        const uint4* p = reinterpret_cast<const uint4*>(&g_wh[(size_t)r * IN_CH + h * 16]);
        uint4 v0 = p[0], v1 = p[1];
        *reinterpret_cast<uint4*>(&hv[0]) = v0;
        *reinterpret_cast<uint4*>(&hv[8]) = v1;
    }
    __half out[8];
    unsigned int m16 = 0;
#pragma unroll
    for (int g = 0; g < 4; g++) {
        int idxs[4], cnt = 0;
#pragma unroll
        for (int k = 0; k < 4; k++) {
            unsigned short bits = reinterpret_cast<unsigned short*>(hv)[g * 4 + k];
            if (bits != 0) idxs[cnt++] = k;
        }
        int i0, i1;
        if (cnt >= 2)      { i0 = idxs[0]; i1 = idxs[1]; }
        else if (cnt == 1) { if (idxs[0] < 2) { i0 = 0; i1 = 1; } else { i0 = 2; i1 = 3; } }
        else               { i0 = 0; i1 = 1; }
        out[g * 2]     = hv[g * 4 + i0];
        out[g * 2 + 1] = hv[g * 4 + i1];
        m16 |= (unsigned int)(i0 | (i1 << 2)) << (4 * g);
        // extras -> overflow (exact fixup terms)
        for (int e = 2; e < cnt; e++) {
            int slot = atomicAdd(&g_ocnt[r], 1);
            if (slot < 16) {
                int c = h * 16 + g * 4 + idxs[e];
                g_ofl[r * 16 + slot] =
                    make_int2(c, __float_as_int(__half2float(hv[g * 4 + idxs[e]])));
            }
        }
    }
    *reinterpret_cast<uint4*>(&g_cw[(size_t)r * (IN_CH / 2) + h * 8]) =
        *reinterpret_cast<uint4*>(out);
    // metadata u16: rows (q, q+8) pairing — low half-word = rows with (r&8)==0
    size_t mi = ((size_t)((r >> 4) * 8 + (r & 7)) * 256 + h) * 2 + ((r >> 3) & 1);
    g_mtm[mi] = (unsigned short)m16;
}

// ---------------------------------------------------------------------------
// 3) x prep: fp32 -> fp16 (g_xh) AND fp16 transpose (g_xT), one kernel.
//    Tile 64 b x 64 c, block (32, 8).
// ---------------------------------------------------------------------------
__global__ void k_xprep(const float* __restrict__ x) {
    __shared__ uint32_t t[64][33];
    const int ch0 = blockIdx.x * 32;       // half2 col base
    const int b0  = blockIdx.y * 64;
    const int tx = threadIdx.x, ty = threadIdx.y;
    const float2* x2 = reinterpret_cast<const float2*>(x);
    __half2* xh2 = reinterpret_cast<__half2*>(g_xh);
    __half2* xT2 = reinterpret_cast<__half2*>(g_xT);
#pragma unroll
    for (int j = 0; j < 8; j++) {
        int row = ty + j * 8;
        float2 v = x2[(size_t)(b0 + row) * 2048 + ch0 + tx];
        __half2 h = __float22half2_rn(v);
        xh2[(size_t)(b0 + row) * 2048 + ch0 + tx] = h;
        t[row][tx] = *reinterpret_cast<uint32_t*>(&h);
    }
    __syncthreads();
    const int tid = ty * 32 + tx;
    const int c0 = ch0 * 2;
#pragma unroll
    for (int it = 0; it < 8; it++) {
        int idx = it * 256 + tid;          // 2048 outputs
        int c_l = idx >> 5;                // 0..63
        int i   = idx & 31;                // b-pair 0..31
        int ch  = c_l >> 1, sel = c_l & 1;
        uint32_t u0 = t[2 * i][ch], u1 = t[2 * i + 1][ch];
        unsigned short lo = sel ? (unsigned short)(u0 >> 16) : (unsigned short)(u0 & 0xFFFF);
        unsigned short hi = sel ? (unsigned short)(u1 >> 16) : (unsigned short)(u1 & 0xFFFF);
        uint32_t packed = (uint32_t)lo | ((uint32_t)hi << 16);
        xT2[(size_t)(c0 + c_l) * 4096 + (b0 >> 1) + i] = *reinterpret_cast<__half2*>(&packed);
    }
}

// ---------------------------------------------------------------------------
// 4) fixup: y = bias + overflow terms (spgemm then ADDS its acc into y).
//    CTA: 128 threads, tile = 128 b x 128 o. smem sY[128][129].
// ---------------------------------------------------------------------------
__global__ void __launch_bounds__(128)
k_fix(const float* __restrict__ bias, float* __restrict__ y) {
    extern __shared__ float sY[];
    const int o0 = blockIdx.x * 128;
    const int b0 = blockIdx.y * 128;
    const int tid = threadIdx.x;

    const float bv = bias[o0 + tid];
#pragma unroll 4
    for (int b = 0; b < 128; b++) sY[b * 129 + tid] = bv;
    __syncthreads();

    for (int rl = 0; rl < 128; rl++) {
        const int r = o0 + rl;
        const int cnt = g_ocnt[r] < 16 ? g_ocnt[r] : 16;
        for (int e = 0; e < cnt; e++) {
            int2 ent = g_ofl[r * 16 + e];
            float w = __int_as_float(ent.y);
            float xv = __half2float(g_xT[(size_t)ent.x * BATCH + b0 + tid]);
            sY[tid * 129 + rl] += w * xv;
        }
    }
    __syncthreads();
#pragma unroll 4
    for (int it = 0; it < 128; it++) {
        int b = it, o = tid;
        y[(size_t)(b0 + b) * OUT_CH + o0 + o] = sY[b * 129 + o];
    }
}

// ---------------------------------------------------------------------------
// cp.async loader: one chunk (Acmp 128x64B-in-128B | B 128x128B | meta 1KB)
// ---------------------------------------------------------------------------
__device__ __forceinline__ void load_chunk(uint32_t sbase, int chunk, int stage,
                                           int m0, int n0, int tid) {
    const int k0 = chunk * KC;
    const uint32_t st = sbase + stage * STAGE_BYTES;
#pragma unroll
    for (int it = 0; it < 13; it++) {
        int j = it * NTHREADS + tid;
        if (j >= 1600) break;
        const void* src;
        uint32_t dst;
        if (j < 512) {                         // A cmp: 128 rows x 4 segs
            int r = j >> 2, s = j & 3;
            src = g_cw + (size_t)(m0 + r) * (IN_CH / 2) + chunk * 32 + s * 8;
            dst = st + (uint32_t)(r * 128 + ((s ^ (r & 7)) << 4));
        } else if (j < 1536) {                 // B (=x): 128 rows x 8 segs
            int jb = j - 512;
            int r = jb >> 3, s = jb & 7;
            src = g_xh + (size_t)(n0 + r) * IN_CH + k0 + s * 8;
            dst = st + OFF_B + (uint32_t)(r * 128 + ((s ^ (r & 7)) << 4));
        } else {                               // meta: 64 x 16B
            int jm = j - 1536;                 // rtl = jm>>3, q = jm&7
            src = reinterpret_cast<const char*>(g_mtm)
                + (size_t)(((m0 >> 4) + (jm >> 3)) * 8 + (jm & 7)) * 1024 + chunk * 16;
            dst = st + OFF_M + (uint32_t)(jm * 16);
        }
        asm volatile("cp.async.cg.shared.global [%0], [%1], 16;" :: "r"(dst), "l"(src));
    }
    asm volatile("cp.async.commit_group;" ::: "memory");
}

// ---------------------------------------------------------------------------
// 5) sparse GEMM: D[128 out x 128 batch] += Wsp * x^T ; epilogue adds into y.
// ---------------------------------------------------------------------------
__global__ void __launch_bounds__(NTHREADS, 2)
k_spgemm(float* __restrict__ y) {
    extern __shared__ char smem[];
    const uint32_t sbase = smem_u32(smem);
    const int tid  = threadIdx.x;
    const int warp = tid >> 5;
    const int lane = tid & 31;
    const int wm   = warp >> 1;           // M half (out)
    const int wn   = warp & 1;            // N half (batch)
    const int m0   = blockIdx.x * TMO;    // out base
    const int n0   = blockIdx.y * TNB;    // batch base

    const uint32_t axor = (uint32_t)(lane & 7);
    uint32_t arow[4];
#pragma unroll
    for (int mt = 0; mt < 4; mt++)
        arow[mt] = (uint32_t)((wm * 64 + mt * 16 + (lane & 15)) * 128);
    const uint32_t aseg = (uint32_t)((lane >> 4) & 1);
    uint32_t brow[8];
#pragma unroll
    for (int j = 0; j < 8; j++)
        brow[j] = (uint32_t)((wn * 64 + j * 8 + (lane & 7)) * 128) + OFF_B;
    const uint32_t bseg = (uint32_t)(lane >> 3);
    const uint32_t mbase = OFF_M + (uint32_t)(((wm * 4) * 8 + (lane >> 2)) * 16
                                              + (lane & 1) * 4);

    float acc[4][8][4];
#pragma unroll
    for (int mt = 0; mt < 4; mt++)
#pragma unroll
        for (int j = 0; j < 8; j++)
#pragma unroll
            for (int q = 0; q < 4; q++) acc[mt][j][q] = 0.0f;

    load_chunk(sbase, 0, 0, m0, n0, tid);
    load_chunk(sbase, 1, 1, m0, n0, tid);

    for (int i = 0; i < NCHUNK; i++) {
        if (i < NCHUNK - 1)
            asm volatile("cp.async.wait_group 1;" ::: "memory");
        else
            asm volatile("cp.async.wait_group 0;" ::: "memory");
        __syncthreads();

        if (i + 2 < NCHUNK)
            load_chunk(sbase, i + 2, (i + 2) % NSTAGE, m0, n0, tid);

        const uint32_t st = sbase + (i % NSTAGE) * STAGE_BYTES;

#pragma unroll
        for (int kt = 0; kt < 2; kt++) {       // 2 x k32 per 64-k chunk
            uint32_t a[4][4], e[4];
#pragma unroll
            for (int mt = 0; mt < 4; mt++) {
                uint32_t seg = (uint32_t)(kt * 2) + aseg;
                ldsm4(a[mt], st + arow[mt] + ((seg ^ axor) << 4));
                asm volatile("ld.shared.b32 %0, [%1];"
                             : "=r"(e[mt]) : "r"(st + mbase + mt * 128 + kt * 8));
            }
#pragma unroll
            for (int j = 0; j < 8; j++) {
                uint32_t b[4];
                uint32_t seg = (uint32_t)(kt * 4) + bseg;
                ldsm4(b, st + brow[j] + ((seg ^ axor) << 4));
#pragma unroll
                for (int mt = 0; mt < 4; mt++)
                    mma_sp16(acc[mt][j], a[mt], b, e[mt]);
            }
        }
    }

    // Epilogue: transpose D through smem, then y += D (y holds bias+overflow)
    __syncthreads();
    float* sD = reinterpret_cast<float*>(smem);
#pragma unroll
    for (int mt = 0; mt < 4; mt++) {
        const int ob = wm * 64 + mt * 16 + (lane >> 2);
#pragma unroll
        for (int j = 0; j < 8; j++) {
            const int bb = wn * 64 + j * 8 + 2 * (lane & 3);
            *reinterpret_cast<float2*>(&sD[ob * 130 + bb]) =
                make_float2(acc[mt][j][0], acc[mt][j][1]);
            *reinterpret_cast<float2*>(&sD[(ob + 8) * 130 + bb]) =
                make_float2(acc[mt][j][2], acc[mt][j][3]);
        }
    }
    __syncthreads();
    {
        float* yrow = y + (size_t)(n0 + tid) * OUT_CH + m0;
#pragma unroll 4
        for (int og = 0; og < 32; og++) {
            float4 v = *reinterpret_cast<float4*>(&yrow[og * 4]);
            v.x += sD[(og * 4 + 0) * 130 + tid];
            v.y += sD[(og * 4 + 1) * 130 + tid];
            v.z += sD[(og * 4 + 2) * 130 + tid];
            v.w += sD[(og * 4 + 3) * 130 + tid];
            *reinterpret_cast<float4*>(&yrow[og * 4]) = v;
        }
    }
}

// ---------------------------------------------------------------------------
// Launch (graph-capturable: kernel launches only, default stream)
// ---------------------------------------------------------------------------
extern "C" void kernel_launch(void* const* d_in, const int* in_sizes, int n_in,
                              void* d_out, int out_size) {
    const float* x    = (const float*)d_in[0];
    const float* w    = (const float*)d_in[1];
    const int*   rows = (const int*)  d_in[2];
    const int*   cols = (const int*)  d_in[3];
    const float* bias = (const float*)d_in[4];
    float*       y    = (float*)d_out;
    const int    nnz  = in_sizes[1];

    cudaFuncSetAttribute(k_spgemm, cudaFuncAttributeMaxDynamicSharedMemorySize,
                         SMEM_TOTAL);
    cudaFuncSetAttribute(k_fix, cudaFuncAttributeMaxDynamicSharedMemorySize,
                         FIX_SMEM);

    k_zero_w<<<(int)(((size_t)OUT_CH * IN_CH / 16) / 256), 256>>>();
    k_scatter_w<<<(nnz + 255) / 256, 256>>>(w, rows, cols, nnz);
    k_compress<<<(OUT_CH * (IN_CH / 16)) / 256, 256>>>();
    k_xprep<<<dim3(IN_CH / 64, BATCH / 64), dim3(32, 8)>>>(x);
    k_fix<<<dim3(OUT_CH / 128, BATCH / 128), 128, FIX_SMEM>>>(bias, y);
    k_spgemm<<<dim3(OUT_CH / TMO, BATCH / TNB), NTHREADS, SMEM_TOTAL>>>(y);
}